// round 2
// baseline (speedup 1.0000x reference)
#include <cuda_runtime.h>

#define BATCH 512
#define TLEN  512
#define IDIM  128
#define HDIM  512

#define NCTA   128
#define BM     64
#define BH     32
#define BK     32
#define NTILES 20          // 4 x-tiles (K=128) + 16 h-tiles (K=512)
#define AS_STRIDE 68
#define WS_STRIDE 132

// Persistent state: ping-pong h. c lives in registers.
__device__ float    g_h[2][BATCH * HDIM];
__device__ unsigned g_count;
__device__ unsigned g_gen;

typedef unsigned long long ull;

__device__ __forceinline__ ull pack2(float x) {
    ull r; unsigned xb = __float_as_uint(x);
    asm("mov.b64 %0, {%1, %1};" : "=l"(r) : "r"(xb));
    return r;
}
__device__ __forceinline__ void fma2(ull& d, ull a, ull b) {
    asm("fma.rn.f32x2 %0, %1, %2, %0;" : "+l"(d) : "l"(a), "l"(b));
}
__device__ __forceinline__ float2 unpack2(ull v) {
    float lo, hi;
    asm("mov.b64 {%0, %1}, %2;" : "=f"(lo), "=f"(hi) : "l"(v));
    return make_float2(lo, hi);
}
__device__ __forceinline__ float sigmoidf_(float x) {
    return 1.0f / (1.0f + expf(-x));
}

// Grid-wide barrier: fenced counter + generation spin. All 128 CTAs are
// co-resident (1 CTA/SM), so spinning is deadlock-free.
__device__ __forceinline__ void grid_barrier() {
    __syncthreads();
    if (threadIdx.x == 0) {
        __threadfence();
        unsigned my = *(volatile unsigned*)&g_gen;
        if (atomicAdd(&g_count, 1u) == NCTA - 1) {
            g_count = 0;
            __threadfence();
            *(volatile unsigned*)&g_gen = my + 1;
        } else {
            while (*(volatile unsigned*)&g_gen == my) { }
        }
        __threadfence();
    }
    __syncthreads();
}

__global__ __launch_bounds__(256, 1) void lstm_persistent(
    const float* __restrict__ x,
    const float* __restrict__ eWih, const float* __restrict__ eWhh,
    const float* __restrict__ ebih, const float* __restrict__ ebhh,
    const float* __restrict__ dWih, const float* __restrict__ dWhh,
    const float* __restrict__ dbih, const float* __restrict__ dbhh,
    const float* __restrict__ fcW,  const float* __restrict__ fcb,
    float* __restrict__ out)
{
    __shared__ __align__(16) float As[BK * AS_STRIDE];   // [k][m^swz]
    __shared__ __align__(16) float Ws[BK * WS_STRIDE];   // [k][gatecol^swz]

    const int tid    = threadIdx.x;
    const int tx     = tid & 15;          // 16 col-groups (2 h-cols each, x4 gates)
    const int ty     = tid >> 4;          // 16 row-groups (4 batch rows each)
    const int jb     = blockIdx.x * BH;   // h-slice base
    const int b0     = blockIdx.y * BM;   // batch base
    const int row_in = tid >> 3;          // 0..31 (tile loader row)
    const int col4   = (tid & 7) << 2;    // 0,4,...,28 (tile loader k offset)
    const int hc0    = jb + (tx << 1);

    // ---- zero this CTA's slice of h0 ----
    for (int i = tid; i < BM * BH; i += 256) {
        int r = i >> 5, c = i & 31;
        g_h[0][(b0 + r) * HDIM + jb + c] = 0.0f;
    }

    // ---- hoist bias sums (enc & dec) ----
    float bsum[2][4][2];
    #pragma unroll
    for (int d = 0; d < 2; ++d) {
        const float* bi = d ? dbih : ebih;
        const float* bh = d ? dbhh : ebhh;
        #pragma unroll
        for (int g = 0; g < 4; ++g)
            #pragma unroll
            for (int e = 0; e < 2; ++e)
                bsum[d][g][e] = bi[g * HDIM + hc0 + e] + bh[g * HDIM + hc0 + e];
    }

    // ---- c state in registers for the whole run ----
    float c_reg[4][2];
    #pragma unroll
    for (int r = 0; r < 4; ++r) { c_reg[r][0] = 0.0f; c_reg[r][1] = 0.0f; }

    grid_barrier();   // h0 fully zeroed everywhere

    float4 a_st[2];   // staged A rows (register double buffer)
    float4 w_st[4];   // staged W rows

    #pragma unroll 1
    for (int s = 0; s < 2 * TLEN; ++s) {
        const int    dec  = (s >= TLEN) ? 1 : 0;
        const int    t    = dec ? (s - TLEN) : s;
        const float* Wih  = dec ? dWih : eWih;
        const float* Whh  = dec ? dWhh : eWhh;
        const float* h_in = g_h[s & 1];
        float*       h_out = g_h[(s + 1) & 1];

        ull acc[4][4];
        #pragma unroll
        for (int r = 0; r < 4; ++r)
            #pragma unroll
            for (int g = 0; g < 4; ++g) acc[r][g] = 0ULL;

        // stage a tile's global loads into registers (L2-coherent)
        auto stage = [&](int tile) {
            const float* Ab; size_t lda; const float* W; size_t ldw; int k0;
            if (tile < 4) { k0 = tile * BK;      Ab = x + (size_t)t * IDIM + k0; lda = (size_t)TLEN * IDIM; W = Wih; ldw = IDIM; }
            else          { k0 = (tile - 4) * BK; Ab = h_in + k0;                lda = HDIM;                W = Whh; ldw = HDIM; }
            #pragma unroll
            for (int p = 0; p < 2; ++p) {
                int row = p * 32 + row_in;
                a_st[p] = __ldcg((const float4*)(Ab + (size_t)(b0 + row) * lda + col4));
            }
            #pragma unroll
            for (int p = 0; p < 4; ++p) {
                int rl   = p * 32 + row_in;       // gate-col index 0..127
                int gate = rl >> 5, hoff = rl & 31;
                w_st[p] = __ldcg((const float4*)(W + (size_t)(gate * HDIM + jb + hoff) * ldw + k0 + col4));
            }
        };

        // swizzled transpose-store (conflict-free: banks = 5*col4 + 4j + row_in)
        auto sts = [&]() {
            #pragma unroll
            for (int p = 0; p < 2; ++p) {
                int row = p * 32 + row_in;
                int m   = row ^ col4;             // swz(k)=col4 for k in this float4
                As[(col4 + 0) * AS_STRIDE + m] = a_st[p].x;
                As[(col4 + 1) * AS_STRIDE + m] = a_st[p].y;
                As[(col4 + 2) * AS_STRIDE + m] = a_st[p].z;
                As[(col4 + 3) * AS_STRIDE + m] = a_st[p].w;
            }
            #pragma unroll
            for (int p = 0; p < 4; ++p) {
                int rl = p * 32 + row_in;
                int m  = rl ^ col4;
                Ws[(col4 + 0) * WS_STRIDE + m] = w_st[p].x;
                Ws[(col4 + 1) * WS_STRIDE + m] = w_st[p].y;
                Ws[(col4 + 2) * WS_STRIDE + m] = w_st[p].z;
                Ws[(col4 + 3) * WS_STRIDE + m] = w_st[p].w;
            }
        };

        stage(0);
        #pragma unroll 1
        for (int tile = 0; tile < NTILES; ++tile) {
            __syncthreads();                      // smem free (prev compute done)
            sts();
            __syncthreads();
            if (tile + 1 < NTILES) stage(tile + 1);   // overlaps with compute below

            #pragma unroll
            for (int k = 0; k < BK; ++k) {
                const int swz = ((k >> 2) & 7) << 2;
                const float4 av = *(const float4*)(As + k * AS_STRIDE + ((ty << 2) ^ swz));
                ull a0 = pack2(av.x), a1 = pack2(av.y), a2 = pack2(av.z), a3 = pack2(av.w);
                const float* wr = Ws + k * WS_STRIDE;
                const int wc = (tx << 1) ^ swz;
                ull w0 = *(const ull*)(wr + wc);
                ull w1 = *(const ull*)(wr + 32 + wc);
                ull w2 = *(const ull*)(wr + 64 + wc);
                ull w3 = *(const ull*)(wr + 96 + wc);
                fma2(acc[0][0], a0, w0); fma2(acc[0][1], a0, w1);
                fma2(acc[0][2], a0, w2); fma2(acc[0][3], a0, w3);
                fma2(acc[1][0], a1, w0); fma2(acc[1][1], a1, w1);
                fma2(acc[1][2], a1, w2); fma2(acc[1][3], a1, w3);
                fma2(acc[2][0], a2, w0); fma2(acc[2][1], a2, w1);
                fma2(acc[2][2], a2, w2); fma2(acc[2][3], a2, w3);
                fma2(acc[3][0], a3, w0); fma2(acc[3][1], a3, w1);
                fma2(acc[3][2], a3, w2); fma2(acc[3][3], a3, w3);
            }
        }

        // ---- elementwise gate update; c in registers, h to global ----
        #pragma unroll
        for (int r = 0; r < 4; ++r) {
            const int b = b0 + (ty << 2) + r;
            float2 pi = unpack2(acc[r][0]);
            float2 pf = unpack2(acc[r][1]);
            float2 pg = unpack2(acc[r][2]);
            float2 po = unpack2(acc[r][3]);
            float hv[2];
            #pragma unroll
            for (int e = 0; e < 2; ++e) {
                float iv = sigmoidf_((e ? pi.y : pi.x) + bsum[dec][0][e]);
                float fv = sigmoidf_((e ? pf.y : pf.x) + bsum[dec][1][e]);
                float gv = tanhf(    (e ? pg.y : pg.x) + bsum[dec][2][e]);
                float ov = sigmoidf_((e ? po.y : po.x) + bsum[dec][3][e]);
                float cn = fv * c_reg[r][e] + iv * gv;
                c_reg[r][e] = cn;
                hv[e] = ov * tanhf(cn);
            }
            *(float2*)(h_out + (size_t)b * HDIM + hc0) = make_float2(hv[0], hv[1]);
        }

        grid_barrier();   // h_out visible everywhere before next step
    }

    // ---- fc epilogue: out[b] = dot(h_last[b,:], fcW) + fcb; h_last = g_h[0] ----
    if (blockIdx.x == 0) {
        const int warp = tid >> 5, lane = tid & 31;
        for (int r = warp; r < BM; r += 8) {
            const float* hr = g_h[0] + (size_t)(b0 + r) * HDIM;
            float ssum = 0.0f;
            #pragma unroll 4
            for (int k = lane; k < HDIM; k += 32)
                ssum += __ldcg(hr + k) * fcW[k];
            #pragma unroll
            for (int o = 16; o; o >>= 1) ssum += __shfl_xor_sync(0xffffffffu, ssum, o);
            if (lane == 0) out[b0 + r] = ssum + fcb[0];
        }
    }
}

extern "C" void kernel_launch(void* const* d_in, const int* in_sizes, int n_in,
                              void* d_out, int out_size)
{
    (void)in_sizes; (void)n_in; (void)out_size;
    const float* x    = (const float*)d_in[0];
    const float* eWih = (const float*)d_in[1];
    const float* eWhh = (const float*)d_in[2];
    const float* ebih = (const float*)d_in[3];
    const float* ebhh = (const float*)d_in[4];
    const float* dWih = (const float*)d_in[5];
    const float* dWhh = (const float*)d_in[6];
    const float* dbih = (const float*)d_in[7];
    const float* dbhh = (const float*)d_in[8];
    const float* fcW  = (const float*)d_in[9];
    const float* fcb  = (const float*)d_in[10];
    float* out = (float*)d_out;

    dim3 grid(HDIM / BH, BATCH / BM);   // (16, 8) = 128 CTAs, 1 per SM
    lstm_persistent<<<grid, 256>>>(x, eWih, eWhh, ebih, ebhh,
                                   dWih, dWhh, dbih, dbhh, fcW, fcb, out);
}

// round 3
// speedup vs baseline: 1.0004x; 1.0004x over previous
#include <cuda_runtime.h>

#define BATCH 512
#define TLEN  512
#define IDIM  128
#define HDIM  512

#define NCTA   128
#define BM     64
#define BH     32
#define BK     32
#define NTILES 20          // 4 x-tiles (K=128) + 16 h-tiles (K=512)
#define AS_STRIDE 68
#define WS_STRIDE 132

// Persistent state: ping-pong h. c lives in registers.
__device__ float    g_h[2][BATCH * HDIM];
__device__ unsigned g_count;
__device__ unsigned g_gen;

typedef unsigned long long ull;

__device__ __forceinline__ ull pack2(float x) {
    ull r; unsigned xb = __float_as_uint(x);
    asm("mov.b64 %0, {%1, %1};" : "=l"(r) : "r"(xb));
    return r;
}
__device__ __forceinline__ void fma2(ull& d, ull a, ull b) {
    asm("fma.rn.f32x2 %0, %1, %2, %0;" : "+l"(d) : "l"(a), "l"(b));
}
__device__ __forceinline__ float2 unpack2(ull v) {
    float lo, hi;
    asm("mov.b64 {%0, %1}, %2;" : "=f"(lo), "=f"(hi) : "l"(v));
    return make_float2(lo, hi);
}
__device__ __forceinline__ float sigmoidf_(float x) {
    return 1.0f / (1.0f + expf(-x));
}

// Grid-wide barrier: fenced counter + generation spin. All 128 CTAs are
// co-resident (1 CTA/SM), so spinning is deadlock-free.
__device__ __forceinline__ void grid_barrier() {
    __syncthreads();
    if (threadIdx.x == 0) {
        __threadfence();
        unsigned my = *(volatile unsigned*)&g_gen;
        if (atomicAdd(&g_count, 1u) == NCTA - 1) {
            g_count = 0;
            __threadfence();
            *(volatile unsigned*)&g_gen = my + 1;
        } else {
            while (*(volatile unsigned*)&g_gen == my) { }
        }
        __threadfence();
    }
    __syncthreads();
}

__global__ __launch_bounds__(256, 1) void lstm_persistent(
    const float* __restrict__ x,
    const float* __restrict__ eWih, const float* __restrict__ eWhh,
    const float* __restrict__ ebih, const float* __restrict__ ebhh,
    const float* __restrict__ dWih, const float* __restrict__ dWhh,
    const float* __restrict__ dbih, const float* __restrict__ dbhh,
    const float* __restrict__ fcW,  const float* __restrict__ fcb,
    float* __restrict__ out)
{
    __shared__ __align__(16) float As[BK * AS_STRIDE];   // [k][m^swz]
    __shared__ __align__(16) float Ws[BK * WS_STRIDE];   // [k][gatecol^swz]

    const int tid    = threadIdx.x;
    const int tx     = tid & 15;          // 16 col-groups (2 h-cols each, x4 gates)
    const int ty     = tid >> 4;          // 16 row-groups (4 batch rows each)
    const int jb     = blockIdx.x * BH;   // h-slice base
    const int b0     = blockIdx.y * BM;   // batch base
    const int row_in = tid >> 3;          // 0..31 (tile loader row)
    const int col4   = (tid & 7) << 2;    // 0,4,...,28 (tile loader k offset)
    const int hc0    = jb + (tx << 1);

    // ---- zero this CTA's slice of h0 ----
    for (int i = tid; i < BM * BH; i += 256) {
        int r = i >> 5, c = i & 31;
        g_h[0][(b0 + r) * HDIM + jb + c] = 0.0f;
    }

    // ---- hoist bias sums (enc & dec) ----
    float bsum[2][4][2];
    #pragma unroll
    for (int d = 0; d < 2; ++d) {
        const float* bi = d ? dbih : ebih;
        const float* bh = d ? dbhh : ebhh;
        #pragma unroll
        for (int g = 0; g < 4; ++g)
            #pragma unroll
            for (int e = 0; e < 2; ++e)
                bsum[d][g][e] = bi[g * HDIM + hc0 + e] + bh[g * HDIM + hc0 + e];
    }

    // ---- c state in registers for the whole run ----
    float c_reg[4][2];
    #pragma unroll
    for (int r = 0; r < 4; ++r) { c_reg[r][0] = 0.0f; c_reg[r][1] = 0.0f; }

    grid_barrier();   // h0 fully zeroed everywhere

    float4 a_st[2];   // staged A rows (register double buffer)
    float4 w_st[4];   // staged W rows

    #pragma unroll 1
    for (int s = 0; s < 2 * TLEN; ++s) {
        const int    dec  = (s >= TLEN) ? 1 : 0;
        const int    t    = dec ? (s - TLEN) : s;
        const float* Wih  = dec ? dWih : eWih;
        const float* Whh  = dec ? dWhh : eWhh;
        const float* h_in = g_h[s & 1];
        float*       h_out = g_h[(s + 1) & 1];

        ull acc[4][4];
        #pragma unroll
        for (int r = 0; r < 4; ++r)
            #pragma unroll
            for (int g = 0; g < 4; ++g) acc[r][g] = 0ULL;

        // stage a tile's global loads into registers (L2-coherent)
        auto stage = [&](int tile) {
            const float* Ab; size_t lda; const float* W; size_t ldw; int k0;
            if (tile < 4) { k0 = tile * BK;      Ab = x + (size_t)t * IDIM + k0; lda = (size_t)TLEN * IDIM; W = Wih; ldw = IDIM; }
            else          { k0 = (tile - 4) * BK; Ab = h_in + k0;                lda = HDIM;                W = Whh; ldw = HDIM; }
            #pragma unroll
            for (int p = 0; p < 2; ++p) {
                int row = p * 32 + row_in;
                a_st[p] = __ldcg((const float4*)(Ab + (size_t)(b0 + row) * lda + col4));
            }
            #pragma unroll
            for (int p = 0; p < 4; ++p) {
                int rl   = p * 32 + row_in;       // gate-col index 0..127
                int gate = rl >> 5, hoff = rl & 31;
                w_st[p] = __ldcg((const float4*)(W + (size_t)(gate * HDIM + jb + hoff) * ldw + k0 + col4));
            }
        };

        // swizzled transpose-store (conflict-free: banks = 5*col4 + 4j + row_in)
        auto sts = [&]() {
            #pragma unroll
            for (int p = 0; p < 2; ++p) {
                int row = p * 32 + row_in;
                int m   = row ^ col4;             // swz(k)=col4 for k in this float4
                As[(col4 + 0) * AS_STRIDE + m] = a_st[p].x;
                As[(col4 + 1) * AS_STRIDE + m] = a_st[p].y;
                As[(col4 + 2) * AS_STRIDE + m] = a_st[p].z;
                As[(col4 + 3) * AS_STRIDE + m] = a_st[p].w;
            }
            #pragma unroll
            for (int p = 0; p < 4; ++p) {
                int rl = p * 32 + row_in;
                int m  = rl ^ col4;
                Ws[(col4 + 0) * WS_STRIDE + m] = w_st[p].x;
                Ws[(col4 + 1) * WS_STRIDE + m] = w_st[p].y;
                Ws[(col4 + 2) * WS_STRIDE + m] = w_st[p].z;
                Ws[(col4 + 3) * WS_STRIDE + m] = w_st[p].w;
            }
        };

        stage(0);
        #pragma unroll 1
        for (int tile = 0; tile < NTILES; ++tile) {
            __syncthreads();                      // smem free (prev compute done)
            sts();
            __syncthreads();
            if (tile + 1 < NTILES) stage(tile + 1);   // overlaps with compute below

            #pragma unroll
            for (int k = 0; k < BK; ++k) {
                const int swz = ((k >> 2) & 7) << 2;
                const float4 av = *(const float4*)(As + k * AS_STRIDE + ((ty << 2) ^ swz));
                ull a0 = pack2(av.x), a1 = pack2(av.y), a2 = pack2(av.z), a3 = pack2(av.w);
                const float* wr = Ws + k * WS_STRIDE;
                const int wc = (tx << 1) ^ swz;
                ull w0 = *(const ull*)(wr + wc);
                ull w1 = *(const ull*)(wr + 32 + wc);
                ull w2 = *(const ull*)(wr + 64 + wc);
                ull w3 = *(const ull*)(wr + 96 + wc);
                fma2(acc[0][0], a0, w0); fma2(acc[0][1], a0, w1);
                fma2(acc[0][2], a0, w2); fma2(acc[0][3], a0, w3);
                fma2(acc[1][0], a1, w0); fma2(acc[1][1], a1, w1);
                fma2(acc[1][2], a1, w2); fma2(acc[1][3], a1, w3);
                fma2(acc[2][0], a2, w0); fma2(acc[2][1], a2, w1);
                fma2(acc[2][2], a2, w2); fma2(acc[2][3], a2, w3);
                fma2(acc[3][0], a3, w0); fma2(acc[3][1], a3, w1);
                fma2(acc[3][2], a3, w2); fma2(acc[3][3], a3, w3);
            }
        }

        // ---- elementwise gate update; c in registers, h to global ----
        #pragma unroll
        for (int r = 0; r < 4; ++r) {
            const int b = b0 + (ty << 2) + r;
            float2 pi = unpack2(acc[r][0]);
            float2 pf = unpack2(acc[r][1]);
            float2 pg = unpack2(acc[r][2]);
            float2 po = unpack2(acc[r][3]);
            float hv[2];
            #pragma unroll
            for (int e = 0; e < 2; ++e) {
                float iv = sigmoidf_((e ? pi.y : pi.x) + bsum[dec][0][e]);
                float fv = sigmoidf_((e ? pf.y : pf.x) + bsum[dec][1][e]);
                float gv = tanhf(    (e ? pg.y : pg.x) + bsum[dec][2][e]);
                float ov = sigmoidf_((e ? po.y : po.x) + bsum[dec][3][e]);
                float cn = fv * c_reg[r][e] + iv * gv;
                c_reg[r][e] = cn;
                hv[e] = ov * tanhf(cn);
            }
            *(float2*)(h_out + (size_t)b * HDIM + hc0) = make_float2(hv[0], hv[1]);
        }

        grid_barrier();   // h_out visible everywhere before next step
    }

    // ---- fc epilogue: out[b] = dot(h_last[b,:], fcW) + fcb; h_last = g_h[0] ----
    if (blockIdx.x == 0) {
        const int warp = tid >> 5, lane = tid & 31;
        for (int r = warp; r < BM; r += 8) {
            const float* hr = g_h[0] + (size_t)(b0 + r) * HDIM;
            float ssum = 0.0f;
            #pragma unroll 4
            for (int k = lane; k < HDIM; k += 32)
                ssum += __ldcg(hr + k) * fcW[k];
            #pragma unroll
            for (int o = 16; o; o >>= 1) ssum += __shfl_xor_sync(0xffffffffu, ssum, o);
            if (lane == 0) out[b0 + r] = ssum + fcb[0];
        }
    }
}

extern "C" void kernel_launch(void* const* d_in, const int* in_sizes, int n_in,
                              void* d_out, int out_size)
{
    (void)in_sizes; (void)n_in; (void)out_size;
    const float* x    = (const float*)d_in[0];
    const float* eWih = (const float*)d_in[1];
    const float* eWhh = (const float*)d_in[2];
    const float* ebih = (const float*)d_in[3];
    const float* ebhh = (const float*)d_in[4];
    const float* dWih = (const float*)d_in[5];
    const float* dWhh = (const float*)d_in[6];
    const float* dbih = (const float*)d_in[7];
    const float* dbhh = (const float*)d_in[8];
    const float* fcW  = (const float*)d_in[9];
    const float* fcb  = (const float*)d_in[10];
    float* out = (float*)d_out;

    dim3 grid(HDIM / BH, BATCH / BM);   // (16, 8) = 128 CTAs, 1 per SM
    lstm_persistent<<<grid, 256>>>(x, eWih, eWhh, ebih, ebhh,
                                   dWih, dWhh, dbih, dbhh, fcW, fcb, out);
}

// round 5
// speedup vs baseline: 1.6548x; 1.6541x over previous
#include <cuda_runtime.h>
#include <cuda_bf16.h>
#include <cstdint>

#define BATCH 512
#define TLEN  512
#define IDIM  128
#define HDIM  512
#define NCTA  128

#define OFF_BSUM  0
#define OFF_WH    1024
#define OFF_WL    (OFF_WH + 81920)
#define OFF_A     (OFF_WL + 81920)       // 164864
#define ATILE     16384                  // 128 rows x 128B (64 bf16)
#define SMEM_BYTES (OFF_A + 4 * ATILE)   // 230400

__device__ float    g_h[2][BATCH * HDIM];
__device__ unsigned g_count, g_gen;

__device__ __forceinline__ uint32_t smem_u32(const void* p) {
    uint32_t a;
    asm("{ .reg .u64 t; cvta.to.shared.u64 t, %1; cvt.u32.u64 %0, t; }" : "=r"(a) : "l"(p));
    return a;
}
#define SWZ(o) ((o) ^ (((o) >> 3) & 0x70))

__device__ __forceinline__ void ldm4(uint32_t* r, uint32_t addr) {
    asm volatile("ldmatrix.sync.aligned.m8n8.x4.shared.b16 {%0,%1,%2,%3}, [%4];"
        : "=r"(r[0]), "=r"(r[1]), "=r"(r[2]), "=r"(r[3]) : "r"(addr));
}
__device__ __forceinline__ void mma16816(float* d, const uint32_t* a, const uint32_t* b) {
    asm volatile("mma.sync.aligned.m16n8k16.row.col.f32.bf16.bf16.f32 "
        "{%0,%1,%2,%3},{%4,%5,%6,%7},{%8,%9},{%0,%1,%2,%3};"
        : "+f"(d[0]), "+f"(d[1]), "+f"(d[2]), "+f"(d[3])
        : "r"(a[0]), "r"(a[1]), "r"(a[2]), "r"(a[3]), "r"(b[0]), "r"(b[1]));
}

__device__ __forceinline__ void grid_barrier() {
    __syncthreads();
    if (threadIdx.x == 0) {
        __threadfence();
        unsigned my = *(volatile unsigned*)&g_gen;
        if (atomicAdd(&g_count, 1u) == NCTA - 1) {
            g_count = 0;
            __threadfence();
            *(volatile unsigned*)&g_gen = my + 1;
        } else {
            while (*(volatile unsigned*)&g_gen == my) { }
        }
        __threadfence();
    }
    __syncthreads();
}

// hi/lo bf16 split of a float4, stored as two 8-byte shared words.
__device__ __forceinline__ void cvt_sts(float4 v, uint32_t ah, uint32_t al) {
    __nv_bfloat162 h0 = __floats2bfloat162_rn(v.x, v.y);
    __nv_bfloat162 h1 = __floats2bfloat162_rn(v.z, v.w);
    float lx = v.x - __bfloat162float(h0.x), ly = v.y - __bfloat162float(h0.y);
    float lz = v.z - __bfloat162float(h1.x), lw = v.w - __bfloat162float(h1.y);
    __nv_bfloat162 l0 = __floats2bfloat162_rn(lx, ly);
    __nv_bfloat162 l1 = __floats2bfloat162_rn(lz, lw);
    uint64_t hv = ((uint64_t)*(uint32_t*)&h1 << 32) | *(uint32_t*)&h0;
    uint64_t lv = ((uint64_t)*(uint32_t*)&l1 << 32) | *(uint32_t*)&l0;
    asm volatile("st.shared.b64 [%0], %1;" :: "r"(ah), "l"(hv) : "memory");
    asm volatile("st.shared.b64 [%0], %1;" :: "r"(al), "l"(lv) : "memory");
}

__device__ __forceinline__ float sig_(float x) { return 1.0f / (1.0f + __expf(-x)); }
__device__ __forceinline__ float tnh_(float x) { return 2.0f / (1.0f + __expf(-2.0f * x)) - 1.0f; }

__global__ void __launch_bounds__(256, 1) lstm_mma(
    const float* __restrict__ x,
    const float* __restrict__ eWih, const float* __restrict__ eWhh,
    const float* __restrict__ ebih, const float* __restrict__ ebhh,
    const float* __restrict__ dWih, const float* __restrict__ dWhh,
    const float* __restrict__ dbih, const float* __restrict__ dbhh,
    const float* __restrict__ fcW,  const float* __restrict__ fcb,
    float* __restrict__ out)
{
    extern __shared__ __align__(1024) char smem[];
    const uint32_t sb = smem_u32(smem);
    const int tid = threadIdx.x, wid = tid >> 5, lane = tid & 31;
    const int jb = blockIdx.x * 16;     // h-col base (32 slices)
    const int b0 = blockIdx.y * 128;    // batch base (4 groups)

    float* bsum = (float*)(smem + OFF_BSUM);

    // zero this CTA's slice of h0
    for (int i = tid; i < 2048; i += 256) {
        int r = i >> 4, c = i & 15;
        g_h[0][(size_t)(b0 + r) * HDIM + jb + c] = 0.0f;
    }

    // c-state in registers: [rp][np][e] (2 rows x 2 nt-parities x 2 cols)
    float cst[8];
    #pragma unroll
    for (int j = 0; j < 8; ++j) cst[j] = 0.0f;

    grid_barrier();

    float4 ra[8], rb[8];
    const int qrow  = lane >> 2;          // 0..7
    const int qcol2 = (lane & 3) << 1;    // 0,2,4,6

    #pragma unroll 1
    for (int s = 0; s < 2 * TLEN; ++s) {
        const int dec = (s >= TLEN) ? 1 : 0;
        const int t = dec ? s - TLEN : s;
        const float* hin  = g_h[s & 1];
        float*       hout = g_h[(s + 1) & 1];

        // ---- per-phase weight + bias preload into SMEM (hi/lo bf16) ----
        if (s == 0 || s == TLEN) {
            const float* Wih = dec ? dWih : eWih;
            const float* Whh = dec ? dWhh : eWhh;
            const float* bi  = dec ? dbih : ebih;
            const float* bh  = dec ? dbhh : ebhh;
            #pragma unroll 1
            for (int i = tid; i < 10240; i += 256) {   // 64 rows x 160 float4
                int rl = i / 160, k4 = i % 160;
                int c = k4 >> 4, kin = k4 & 15;
                int grow = (rl >> 4) * HDIM + jb + (rl & 15);
                const float* sp = (c < 2) ? (Wih + (size_t)grow * IDIM + c * 64 + kin * 4)
                                          : (Whh + (size_t)grow * HDIM + (c - 2) * 64 + kin * 4);
                float4 v = *(const float4*)sp;
                uint32_t off = (uint32_t)c * 8192u + SWZ((uint32_t)rl * 128u + (uint32_t)kin * 8u);
                cvt_sts(v, sb + OFF_WH + off, sb + OFF_WL + off);
            }
            if (tid < 64) {
                int g = tid >> 4, j = tid & 15;
                bsum[tid] = bi[g * HDIM + jb + j] + bh[g * HDIM + jb + j];
            }
            __syncthreads();
        }

        float acc[8][4];
        #pragma unroll
        for (int nt = 0; nt < 8; ++nt)
            #pragma unroll
            for (int q = 0; q < 4; ++q) acc[nt][q] = 0.0f;

        auto stage = [&](int c, float4* rg) {
            const float* src; size_t rs;
            if (c < 2) { src = x + (size_t)b0 * TLEN * IDIM + (size_t)t * IDIM + c * 64; rs = (size_t)TLEN * IDIM; }
            else       { src = hin + (size_t)b0 * HDIM + (c - 2) * 64; rs = HDIM; }
            #pragma unroll
            for (int i = 0; i < 8; ++i) {
                int f = i * 256 + tid;
                rg[i] = __ldcg((const float4*)(src + (size_t)(f >> 4) * rs + (f & 15) * 4));
            }
        };
        auto sts = [&](int c, float4* rg) {
            uint32_t abh = sb + OFF_A + (uint32_t)(c & 1) * (2 * ATILE);
            uint32_t abl = abh + ATILE;
            #pragma unroll
            for (int i = 0; i < 8; ++i) {
                int f = i * 256 + tid;
                uint32_t off = SWZ((uint32_t)(f >> 4) * 128u + (uint32_t)(f & 15) * 8u);
                cvt_sts(rg[i], abh + off, abl + off);
            }
        };
        auto compute = [&](int c) {
            uint32_t abase = sb + OFF_A + (uint32_t)(c & 1) * (2 * ATILE);
            uint32_t wbase = sb + OFF_WH + (uint32_t)c * 8192u;
            #pragma unroll
            for (int ks = 0; ks < 4; ++ks) {
                uint32_t ah[4], al[4], bh[16], bl[16];
                uint32_t aoff = SWZ((uint32_t)(wid * 16 + (lane & 15)) * 128u
                                    + (uint32_t)ks * 32u + ((lane & 16) ? 16u : 0u));
                ldm4(ah, abase + aoff);
                ldm4(al, abase + aoff + ATILE);
                #pragma unroll
                for (int p = 0; p < 4; ++p) {
                    uint32_t brow = (uint32_t)(p * 16 + ((lane & 16) ? 8 : 0) + (lane & 7));
                    uint32_t boff = SWZ(brow * 128u + (uint32_t)ks * 32u + ((lane & 8) ? 16u : 0u));
                    ldm4(bh + 4 * p, wbase + boff);
                    ldm4(bl + 4 * p, wbase + boff + 81920u);
                }
                #pragma unroll
                for (int nt = 0; nt < 8; ++nt) {
                    mma16816(acc[nt], ah, bh + 2 * nt);
                    mma16816(acc[nt], al, bh + 2 * nt);
                    mma16816(acc[nt], ah, bl + 2 * nt);
                }
            }
        };

        stage(0, ra);
        #pragma unroll 1
        for (int c = 0; c < 10; ++c) {
            float4* cur = (c & 1) ? rb : ra;
            float4* nxt = (c & 1) ? ra : rb;
            sts(c, cur);
            __syncthreads();
            if (c < 9) stage(c + 1, nxt);
            compute(c);
        }

        // ---- fused gate epilogue (accumulators already in registers) ----
        #pragma unroll
        for (int rp = 0; rp < 2; ++rp) {
            const int m = wid * 16 + qrow + rp * 8;
            float* hp = hout + (size_t)(b0 + m) * HDIM + jb;
            #pragma unroll
            for (int np = 0; np < 2; ++np) {
                const int hb = np * 8 + qcol2;
                float hv[2];
                #pragma unroll
                for (int e = 0; e < 2; ++e) {
                    const int ci = 2 * rp + e;
                    float pi = acc[0 + np][ci] + bsum[hb + e];
                    float pf = acc[2 + np][ci] + bsum[16 + hb + e];
                    float pg = acc[4 + np][ci] + bsum[32 + hb + e];
                    float po = acc[6 + np][ci] + bsum[48 + hb + e];
                    float iv = sig_(pi), fv = sig_(pf), gv = tnh_(pg), ov = sig_(po);
                    const int cs = rp * 4 + np * 2 + e;
                    float cn = fv * cst[cs] + iv * gv;
                    cst[cs] = cn;
                    hv[e] = ov * tnh_(cn);
                }
                *(float2*)(hp + hb) = make_float2(hv[0], hv[1]);
            }
        }
        grid_barrier();
    }

    // ---- fc epilogue: final h is in g_h[0] ----
    if (blockIdx.x == 0) {
        for (int r = wid; r < 128; r += 8) {
            const float* hr = g_h[0] + (size_t)(b0 + r) * HDIM;
            float ssum = 0.0f;
            #pragma unroll 4
            for (int k = lane; k < HDIM; k += 32) ssum += __ldcg(hr + k) * fcW[k];
            #pragma unroll
            for (int o = 16; o; o >>= 1) ssum += __shfl_xor_sync(0xffffffffu, ssum, o);
            if (lane == 0) out[b0 + r] = ssum + fcb[0];
        }
    }
}

extern "C" void kernel_launch(void* const* d_in, const int* in_sizes, int n_in,
                              void* d_out, int out_size)
{
    (void)in_sizes; (void)n_in; (void)out_size;
    cudaFuncSetAttribute(lstm_mma, cudaFuncAttributeMaxDynamicSharedMemorySize, SMEM_BYTES);
    dim3 grid(32, 4);   // 32 h-col slices x 4 batch groups = 128 CTAs (1/SM)
    lstm_mma<<<grid, 256, SMEM_BYTES>>>(
        (const float*)d_in[0],
        (const float*)d_in[1], (const float*)d_in[2],
        (const float*)d_in[3], (const float*)d_in[4],
        (const float*)d_in[5], (const float*)d_in[6],
        (const float*)d_in[7], (const float*)d_in[8],
        (const float*)d_in[9], (const float*)d_in[10],
        (float*)d_out);
}

// round 6
// speedup vs baseline: 1.7952x; 1.0849x over previous
#include <cuda_runtime.h>
#include <cuda_bf16.h>
#include <cstdint>

#define BATCH 512
#define TLEN  512
#define IDIM  128
#define HDIM  512
#define NCTA  128

#define OFF_BSUM  0
#define OFF_XCH   1024                    // 4 pairs * 32 rows * 72 f32 * 4B = 36864
#define OFF_WH    38912
#define OFF_WL    (OFF_WH + 81920)
#define SMEM_BYTES (OFF_WL + 81920)       // 202752

__device__ float    g_h[2][BATCH * HDIM];
__device__ unsigned g_count, g_gen;

__device__ __forceinline__ uint32_t smem_u32(const void* p) {
    uint32_t a;
    asm("{ .reg .u64 t; cvta.to.shared.u64 t, %1; cvt.u32.u64 %0, t; }" : "=r"(a) : "l"(p));
    return a;
}
#define SWZ(o) ((o) ^ (((o) >> 3) & 0x70))

__device__ __forceinline__ void ldm4(uint32_t* r, uint32_t addr) {
    asm volatile("ldmatrix.sync.aligned.m8n8.x4.shared.b16 {%0,%1,%2,%3}, [%4];"
        : "=r"(r[0]), "=r"(r[1]), "=r"(r[2]), "=r"(r[3]) : "r"(addr));
}
__device__ __forceinline__ void mma16816(float* d, const uint32_t* a, const uint32_t* b) {
    asm volatile("mma.sync.aligned.m16n8k16.row.col.f32.bf16.bf16.f32 "
        "{%0,%1,%2,%3},{%4,%5,%6,%7},{%8,%9},{%0,%1,%2,%3};"
        : "+f"(d[0]), "+f"(d[1]), "+f"(d[2]), "+f"(d[3])
        : "r"(a[0]), "r"(a[1]), "r"(a[2]), "r"(a[3]), "r"(b[0]), "r"(b[1]));
}

// ---- monotonic grid barrier: arrive (tid0) / wait-for-absolute-target ----
__device__ __forceinline__ void gb_arrive(int tid) {
    if (tid == 0) {
        __threadfence();
        unsigned my = *(volatile unsigned*)&g_gen;
        if (atomicAdd(&g_count, 1u) == NCTA - 1) {
            g_count = 0;
            __threadfence();
            *(volatile unsigned*)&g_gen = my + 1;
        }
    }
}
__device__ __forceinline__ void gb_wait(int tid, unsigned target) {
    if (tid == 0) {
        while ((int)(*(volatile unsigned*)&g_gen - target) < 0) { }
        __threadfence();
    }
    __syncthreads();
}

// hi/lo bf16 split of a float4, stored as two 8-byte shared words (weights).
__device__ __forceinline__ void cvt_sts(float4 v, uint32_t ah, uint32_t al) {
    __nv_bfloat162 h0 = __floats2bfloat162_rn(v.x, v.y);
    __nv_bfloat162 h1 = __floats2bfloat162_rn(v.z, v.w);
    float lx = v.x - __bfloat162float(h0.x), ly = v.y - __bfloat162float(h0.y);
    float lz = v.z - __bfloat162float(h1.x), lw = v.w - __bfloat162float(h1.y);
    __nv_bfloat162 l0 = __floats2bfloat162_rn(lx, ly);
    __nv_bfloat162 l1 = __floats2bfloat162_rn(lz, lw);
    uint64_t hv = ((uint64_t)*(uint32_t*)&h1 << 32) | *(uint32_t*)&h0;
    uint64_t lv = ((uint64_t)*(uint32_t*)&l1 << 32) | *(uint32_t*)&l0;
    asm volatile("st.shared.b64 [%0], %1;" :: "r"(ah), "l"(hv) : "memory");
    asm volatile("st.shared.b64 [%0], %1;" :: "r"(al), "l"(lv) : "memory");
}

__device__ __forceinline__ float sig_(float x) { return 1.0f / (1.0f + __expf(-x)); }
__device__ __forceinline__ float tnh_(float x) { return 2.0f / (1.0f + __expf(-2.0f * x)) - 1.0f; }

__global__ void __launch_bounds__(256, 1) lstm_mma2(
    const float* __restrict__ x,
    const float* __restrict__ eWih, const float* __restrict__ eWhh,
    const float* __restrict__ ebih, const float* __restrict__ ebhh,
    const float* __restrict__ dWih, const float* __restrict__ dWhh,
    const float* __restrict__ dbih, const float* __restrict__ dbhh,
    const float* __restrict__ fcW,  const float* __restrict__ fcb,
    float* __restrict__ out)
{
    extern __shared__ __align__(1024) char smem[];
    const uint32_t sb = smem_u32(smem);
    const int tid = threadIdx.x, wid = tid >> 5, lane = tid & 31;
    const int p  = wid >> 1;            // pair/tile 0..3 -> rows 32p..32p+31
    const int kp = wid & 1;             // k-parity within pair
    const int jb = blockIdx.x * 16;     // h-col base
    const int b0 = blockIdx.y * 128;    // batch base
    const int lq = lane >> 2;           // 0..7
    const int lr = (lane & 3) << 1;     // 0,2,4,6

    float* bsum = (float*)(smem + OFF_BSUM);
    char*  xch  = smem + OFF_XCH + p * 9216;   // 32 rows x 72 f32 (288B stride)

    unsigned gbase = 0;
    if (tid == 0) gbase = *(volatile unsigned*)&g_gen;

    // zero this CTA's slice of h0
    for (int i = tid; i < 2048; i += 256) {
        int r = i >> 4, c = i & 15;
        g_h[0][(size_t)(b0 + r) * HDIM + jb + c] = 0.0f;
    }
    float cst[16];
    #pragma unroll
    for (int j = 0; j < 16; ++j) cst[j] = 0.0f;

    gb_arrive(tid);
    gb_wait(tid, gbase + 1);

    float2 bufA[16], bufB[16];

    #pragma unroll 1
    for (int s = 0; s < 2 * TLEN; ++s) {
        const int dec = (s >= TLEN) ? 1 : 0;
        const int t = dec ? s - TLEN : s;
        const float* hin  = g_h[s & 1];
        float*       hout = g_h[(s + 1) & 1];

        // ---- per-phase weight + bias preload (hi/lo bf16 in SMEM) ----
        if (s == 0 || s == TLEN) {
            const float* Wih = dec ? dWih : eWih;
            const float* Whh = dec ? dWhh : eWhh;
            const float* bi  = dec ? dbih : ebih;
            const float* bh  = dec ? dbhh : ebhh;
            #pragma unroll 1
            for (int i = tid; i < 10240; i += 256) {   // 64 rows x 160 float4
                int rl = i / 160, k4 = i % 160;
                int c = k4 >> 4, kin = k4 & 15;
                int grow = (rl >> 4) * HDIM + jb + (rl & 15);
                const float* sp = (c < 2) ? (Wih + (size_t)grow * IDIM + c * 64 + kin * 4)
                                          : (Whh + (size_t)grow * HDIM + (c - 2) * 64 + kin * 4);
                float4 v = *(const float4*)sp;
                uint32_t off = (uint32_t)c * 8192u + SWZ((uint32_t)rl * 128u + (uint32_t)kin * 8u);
                cvt_sts(v, sb + OFF_WH + off, sb + OFF_WL + off);
            }
            if (tid < 64) {
                int g = tid >> 4, j = tid & 15;
                bsum[tid] = bi[g * HDIM + jb + j] + bh[g * HDIM + jb + j];
            }
            __syncthreads();
        }

        float acc[2][8][4];
        #pragma unroll
        for (int fi = 0; fi < 2; ++fi)
            #pragma unroll
            for (int nt = 0; nt < 8; ++nt)
                #pragma unroll
                for (int q = 0; q < 4; ++q) acc[fi][nt][q] = 0.0f;

        // prefetch A fragments of chunk c (f32, exact MMA-fragment elements)
        auto pf = [&](int c, float2* buf) {
            const float* base; size_t rs;
            if (c < 2) { base = x + (size_t)b0 * TLEN * IDIM + (size_t)t * IDIM + c * 64; rs = (size_t)TLEN * IDIM; }
            else       { base = hin + (size_t)b0 * HDIM + (c - 2) * 64; rs = HDIM; }
            #pragma unroll
            for (int ki = 0; ki < 2; ++ki) {
                const int ks = kp + 2 * ki;
                #pragma unroll
                for (int fi = 0; fi < 2; ++fi)
                    #pragma unroll
                    for (int q = 0; q < 4; ++q) {
                        int r  = 32 * p + fi * 16 + lq + (q & 1) * 8;
                        int kk = ks * 16 + lr + (q >> 1) * 8;
                        buf[ki * 8 + fi * 4 + q] = __ldcg((const float2*)(base + (size_t)r * rs + kk));
                    }
            }
        };

        auto compute = [&](int c, const float2* buf) {
            const uint32_t wb = sb + OFF_WH + (uint32_t)c * 8192u;
            #pragma unroll
            for (int ki = 0; ki < 2; ++ki) {
                const int ks = kp + 2 * ki;
                uint32_t bh[16], bl[16];
                #pragma unroll
                for (int pp = 0; pp < 4; ++pp) {
                    uint32_t brow = (uint32_t)(pp * 16 + ((lane & 16) ? 8 : 0) + (lane & 7));
                    uint32_t boff = SWZ(brow * 128u + (uint32_t)ks * 32u + ((lane & 8) ? 16u : 0u));
                    ldm4(bh + 4 * pp, wb + boff);
                    ldm4(bl + 4 * pp, wb + 81920u + boff);
                }
                uint32_t ah[2][4], al[2][4];
                #pragma unroll
                for (int fi = 0; fi < 2; ++fi)
                    #pragma unroll
                    for (int q = 0; q < 4; ++q) {
                        float2 v = buf[ki * 8 + fi * 4 + q];
                        __nv_bfloat162 h2 = __floats2bfloat162_rn(v.x, v.y);
                        float rx = v.x - __bfloat162float(h2.x);
                        float ry = v.y - __bfloat162float(h2.y);
                        __nv_bfloat162 l2 = __floats2bfloat162_rn(rx, ry);
                        ah[fi][q] = *(uint32_t*)&h2;
                        al[fi][q] = *(uint32_t*)&l2;
                    }
                #pragma unroll
                for (int fi = 0; fi < 2; ++fi)
                    #pragma unroll
                    for (int nt = 0; nt < 8; ++nt) {
                        mma16816(acc[fi][nt], ah[fi], bh + 2 * nt);
                        mma16816(acc[fi][nt], al[fi], bh + 2 * nt);
                        mma16816(acc[fi][nt], ah[fi], bl + 2 * nt);
                    }
            }
        };

        // x-chunks (h-independent) run before the barrier wait -> overlap
        pf(0, bufA); pf(1, bufB);
        compute(0, bufA);
        compute(1, bufB);
        gb_wait(tid, gbase + 1 + (unsigned)s);   // h from step s-1 ready
        pf(2, bufA);
        #pragma unroll 1
        for (int c = 2; c < 10; ++c) {
            float2* cur = (c & 1) ? bufB : bufA;
            float2* nxt = (c & 1) ? bufA : bufB;
            if (c < 9) pf(c + 1, nxt);
            compute(c, cur);
        }

        // ---- split-K exchange + fused gate epilogue ----
        if (kp) {
            #pragma unroll
            for (int fi = 0; fi < 2; ++fi)
                #pragma unroll
                for (int nt = 0; nt < 8; ++nt)
                    #pragma unroll
                    for (int qr = 0; qr < 2; ++qr) {
                        uint32_t rowl = (uint32_t)(fi * 16 + lq + qr * 8);
                        uint32_t col  = (uint32_t)(nt * 8 + lr);
                        *(float2*)(xch + rowl * 288 + col * 4) =
                            make_float2(acc[fi][nt][2 * qr], acc[fi][nt][2 * qr + 1]);
                    }
        }
        __syncthreads();
        if (!kp) {
            #pragma unroll
            for (int fi = 0; fi < 2; ++fi)
                #pragma unroll
                for (int nt = 0; nt < 8; ++nt)
                    #pragma unroll
                    for (int qr = 0; qr < 2; ++qr) {
                        uint32_t rowl = (uint32_t)(fi * 16 + lq + qr * 8);
                        uint32_t col  = (uint32_t)(nt * 8 + lr);
                        float2 pv = *(const float2*)(xch + rowl * 288 + col * 4);
                        acc[fi][nt][2 * qr]     += pv.x;
                        acc[fi][nt][2 * qr + 1] += pv.y;
                    }
            #pragma unroll
            for (int fi = 0; fi < 2; ++fi)
                #pragma unroll
                for (int qr = 0; qr < 2; ++qr) {
                    const int r = 32 * p + fi * 16 + lq + qr * 8;
                    float* hp = hout + (size_t)(b0 + r) * HDIM + jb;
                    #pragma unroll
                    for (int nh = 0; nh < 2; ++nh) {
                        float hv[2];
                        #pragma unroll
                        for (int e = 0; e < 2; ++e) {
                            const int q = 2 * qr + e;
                            const int j = nh * 8 + lr + e;
                            float pi = acc[fi][nh][q]     + bsum[j];
                            float pf_ = acc[fi][2 + nh][q] + bsum[16 + j];
                            float pg = acc[fi][4 + nh][q] + bsum[32 + j];
                            float po = acc[fi][6 + nh][q] + bsum[48 + j];
                            float iv = sig_(pi), fv = sig_(pf_), gv = tnh_(pg), ov = sig_(po);
                            const int ci = fi * 8 + qr * 4 + nh * 2 + e;
                            float cn = fv * cst[ci] + iv * gv;
                            cst[ci] = cn;
                            hv[e] = ov * tnh_(cn);
                        }
                        *(float2*)(hp + nh * 8 + lr) = make_float2(hv[0], hv[1]);
                    }
                }
            __threadfence();
        }
        __syncthreads();
        gb_arrive(tid);
    }

    // ---- fc epilogue: final h is in g_h[0] ----
    gb_wait(tid, gbase + 1 + 2 * TLEN);
    if (blockIdx.x == 0) {
        for (int r = wid; r < 128; r += 8) {
            const float* hr = g_h[0] + (size_t)(b0 + r) * HDIM;
            float ssum = 0.0f;
            #pragma unroll 4
            for (int k = lane; k < HDIM; k += 32) ssum += __ldcg(hr + k) * fcW[k];
            #pragma unroll
            for (int o = 16; o; o >>= 1) ssum += __shfl_xor_sync(0xffffffffu, ssum, o);
            if (lane == 0) out[b0 + r] = ssum + fcb[0];
        }
    }
}

extern "C" void kernel_launch(void* const* d_in, const int* in_sizes, int n_in,
                              void* d_out, int out_size)
{
    (void)in_sizes; (void)n_in; (void)out_size;
    cudaFuncSetAttribute(lstm_mma2, cudaFuncAttributeMaxDynamicSharedMemorySize, SMEM_BYTES);
    dim3 grid(32, 4);   // 32 h-slices x 4 batch groups = 128 CTAs (1/SM)
    lstm_mma2<<<grid, 256, SMEM_BYTES>>>(
        (const float*)d_in[0],
        (const float*)d_in[1], (const float*)d_in[2],
        (const float*)d_in[3], (const float*)d_in[4],
        (const float*)d_in[5], (const float*)d_in[6],
        (const float*)d_in[7], (const float*)d_in[8],
        (const float*)d_in[9], (const float*)d_in[10],
        (float*)d_out);
}